// round 1
// baseline (speedup 1.0000x reference)
#include <cuda_runtime.h>

#define H 4096
#define HH (H * H)                 // 16777216
#define OUT_ACT  0                 // activout[4]
#define OUT_VAL  4                 // valueout[1]
#define OUT_HACT 5                 // hactiv[4096]
#define OUT_HEBB 4101              // hebb_new[H*H]  (float offset 4101 == 1 mod 4!)

__device__ float g_y[H];           // pre-tanh accumulator
__device__ float g_hact[H];        // aligned copy of hactiv for the hebb kernel

// ---------------------------------------------------------------------------
// Kernel 0: y[j] = bi[j] + sum_k x[k]*Wi[k,j]   (17x4096, tiny)
// ---------------------------------------------------------------------------
__global__ void init_y_kernel(const float* __restrict__ x,
                              const float* __restrict__ Wi,
                              const float* __restrict__ bi) {
    int j = blockIdx.x * blockDim.x + threadIdx.x;
    if (j >= H) return;
    float s = bi[j];
#pragma unroll
    for (int k = 0; k < 17; k++)
        s = fmaf(x[k], Wi[k * H + j], s);
    g_y[j] = s;
}

// ---------------------------------------------------------------------------
// Kernel 1: y[j] += sum_i hidden[i] * (w[i,j] + alpha[i,j]*hebb[i,j])
// Streams 192 MB. grid = (4 col-tiles of 1024 cols, 128 row-chunks of 32 rows)
// ---------------------------------------------------------------------------
__global__ void __launch_bounds__(256)
gemv_acc_kernel(const float* __restrict__ hidden,
                const float* __restrict__ w,
                const float* __restrict__ alpha,
                const float* __restrict__ hebb) {
    int j  = (blockIdx.x * 256 + threadIdx.x) * 4;   // column base (float4)
    int r0 = blockIdx.y * 32;                        // row chunk
    float4 acc = make_float4(0.f, 0.f, 0.f, 0.f);
#pragma unroll 8
    for (int i = r0; i < r0 + 32; ++i) {
        float h = __ldg(hidden + i);                 // broadcast within warp
        size_t off = (size_t)i * H + j;
        float4 wv = *(const float4*)(w + off);
        float4 av = *(const float4*)(alpha + off);
        float4 hv = *(const float4*)(hebb + off);
        acc.x = fmaf(h, fmaf(av.x, hv.x, wv.x), acc.x);
        acc.y = fmaf(h, fmaf(av.y, hv.y, wv.y), acc.y);
        acc.z = fmaf(h, fmaf(av.z, hv.z, wv.z), acc.z);
        acc.w = fmaf(h, fmaf(av.w, hv.w, wv.w), acc.w);
    }
    atomicAdd(&g_y[j + 0], acc.x);
    atomicAdd(&g_y[j + 1], acc.y);
    atomicAdd(&g_y[j + 2], acc.z);
    atomicAdd(&g_y[j + 3], acc.w);
}

// ---------------------------------------------------------------------------
// Kernel 2: hactiv = tanh(y); heads (softmax over 4 actions, value); 1 block.
// ---------------------------------------------------------------------------
__inline__ __device__ float warp_sum(float v) {
#pragma unroll
    for (int o = 16; o > 0; o >>= 1)
        v += __shfl_down_sync(0xffffffffu, v, o);
    return v;
}

__global__ void __launch_bounds__(1024)
finalize_kernel(const float* __restrict__ Wo, const float* __restrict__ bo,
                const float* __restrict__ Wv, const float* __restrict__ bv,
                float* __restrict__ out) {
    int t = threadIdx.x;
    float p0 = 0.f, p1 = 0.f, p2 = 0.f, p3 = 0.f, pv = 0.f;
#pragma unroll
    for (int j = t; j < H; j += 1024) {
        float hact = tanhf(g_y[j]);
        out[OUT_HACT + j] = hact;
        g_hact[j] = hact;
        float4 wo = *(const float4*)(Wo + (size_t)j * 4);  // 16B aligned
        p0 = fmaf(hact, wo.x, p0);
        p1 = fmaf(hact, wo.y, p1);
        p2 = fmaf(hact, wo.z, p2);
        p3 = fmaf(hact, wo.w, p3);
        pv = fmaf(hact, Wv[j], pv);
    }
    __shared__ float sh[5][32];
    int lane = t & 31, wid = t >> 5;
    p0 = warp_sum(p0); p1 = warp_sum(p1); p2 = warp_sum(p2);
    p3 = warp_sum(p3); pv = warp_sum(pv);
    if (lane == 0) {
        sh[0][wid] = p0; sh[1][wid] = p1; sh[2][wid] = p2;
        sh[3][wid] = p3; sh[4][wid] = pv;
    }
    __syncthreads();
    if (wid == 0) {
        float v0 = warp_sum(sh[0][lane]);
        float v1 = warp_sum(sh[1][lane]);
        float v2 = warp_sum(sh[2][lane]);
        float v3 = warp_sum(sh[3][lane]);
        float v4 = warp_sum(sh[4][lane]);
        if (lane == 0) {
            float l0 = v0 + bo[0], l1 = v1 + bo[1], l2 = v2 + bo[2], l3 = v3 + bo[3];
            float m = fmaxf(fmaxf(l0, l1), fmaxf(l2, l3));
            float e0 = expf(l0 - m), e1 = expf(l1 - m), e2 = expf(l2 - m), e3 = expf(l3 - m);
            float inv = 1.0f / (e0 + e1 + e2 + e3);
            out[OUT_ACT + 0] = e0 * inv;
            out[OUT_ACT + 1] = e1 * inv;
            out[OUT_ACT + 2] = e2 * inv;
            out[OUT_ACT + 3] = e3 * inv;
            out[OUT_VAL] = v4 + bv[0];
        }
    }
}

// ---------------------------------------------------------------------------
// Kernel 3: hebb_new[i,j] = (1-eta)*hebb[i,j] + eta*hidden[i]*hactiv[j]
// Output region is misaligned by 1 float (offset 4101). We store OUTPUT-
// aligned float4 chunks covering source indices k = 3+4q .. 6+4q, built from
// two adjacent aligned float4 loads of hebb (overlap hits same L1 line).
// ---------------------------------------------------------------------------
__global__ void __launch_bounds__(256)
hebb_update_kernel(const float* __restrict__ hebb,
                   const float* __restrict__ hidden,
                   const float* __restrict__ eta,
                   float* __restrict__ out) {
    const long long NC = (HH - 4) / 4 + 1;   // 4194303 aligned output chunks
    float et = eta[0];
    float em = 1.0f - et;
    float* ho = out + OUT_HEBB;

    long long q = (long long)blockIdx.x * blockDim.x + threadIdx.x;
    long long stride = (long long)gridDim.x * blockDim.x;

    if (q == 0) {
        // head k = 0..2 (row 0), tail k = HH-1 (row 4095, col 4095)
#pragma unroll
        for (int k = 0; k < 3; k++)
            ho[k] = fmaf(em, hebb[k], et * hidden[0] * g_hact[k]);
        ho[HH - 1] = fmaf(em, hebb[HH - 1], et * hidden[H - 1] * g_hact[H - 1]);
    }

    const float4* hb4 = (const float4*)hebb;
    for (; q < NC; q += stride) {
        long long k = 4 * q + 3;
        float4 A = hb4[q];
        float4 B = hb4[q + 1];
        float s0 = A.w, s1 = B.x, s2 = B.y, s3 = B.z;

        int j0 = (int)(k & (H - 1));
        int i0 = (int)(k >> 12);
        float4 r;
        if (j0 <= H - 4) {
            // fast path: same row for all 4 elements
            float hi = __ldg(hidden + i0) * et;
            r.x = fmaf(em, s0, hi * g_hact[j0 + 0]);
            r.y = fmaf(em, s1, hi * g_hact[j0 + 1]);
            r.z = fmaf(em, s2, hi * g_hact[j0 + 2]);
            r.w = fmaf(em, s3, hi * g_hact[j0 + 3]);
        } else {
            float src[4] = {s0, s1, s2, s3};
            float rr[4];
#pragma unroll
            for (int e = 0; e < 4; e++) {
                long long kk = k + e;
                int i = (int)(kk >> 12);
                int j = (int)(kk & (H - 1));
                rr[e] = fmaf(em, src[e], et * __ldg(hidden + i) * g_hact[j]);
            }
            r = make_float4(rr[0], rr[1], rr[2], rr[3]);
        }
        *(float4*)(ho + k) = r;   // out+4101+k, k==3 mod 4 -> 16B aligned
    }
}

// ---------------------------------------------------------------------------
// inputs: x, hidden, hebb, Wi, bi, w, alpha, eta, Wo, bo, Wv, bv
// output: activout[4] | valueout[1] | hactiv[4096] | hebb_new[4096*4096]
// ---------------------------------------------------------------------------
extern "C" void kernel_launch(void* const* d_in, const int* in_sizes, int n_in,
                              void* d_out, int out_size) {
    const float* x      = (const float*)d_in[0];
    const float* hidden = (const float*)d_in[1];
    const float* hebb   = (const float*)d_in[2];
    const float* Wi     = (const float*)d_in[3];
    const float* bi     = (const float*)d_in[4];
    const float* w      = (const float*)d_in[5];
    const float* alpha  = (const float*)d_in[6];
    const float* eta    = (const float*)d_in[7];
    const float* Wo     = (const float*)d_in[8];
    const float* bo     = (const float*)d_in[9];
    const float* Wv     = (const float*)d_in[10];
    const float* bv     = (const float*)d_in[11];
    float* out = (float*)d_out;

    init_y_kernel<<<H / 256, 256>>>(x, Wi, bi);
    gemv_acc_kernel<<<dim3(4, 128), 256>>>(hidden, w, alpha, hebb);
    finalize_kernel<<<1, 1024>>>(Wo, bo, Wv, bv, out);
    hebb_update_kernel<<<2048, 256>>>(hebb, hidden, eta, out);
}